// round 2
// baseline (speedup 1.0000x reference)
#include <cuda_runtime.h>

// ---------------- problem constants (fixed-shape problem) ----------------
#define NNODES 20000
#define NEDGES 320000
#define ETOT   (NEDGES + NNODES)
#define NGRAPH 64
#define FIN    64
#define HID    64
#define NHEAD  8
#define GFEAT  16
#define NCLS   10
#define NEG    0.2f
#define D1     (NHEAD * HID)   // 512

// ---------------- device scratch (static, no allocation) ----------------
__device__ float g_xl1[(size_t)NNODES * D1];
__device__ float g_xr1[(size_t)NNODES * D1];
__device__ float g_h1 [(size_t)NNODES * D1];
__device__ float g_xl2[(size_t)NNODES * HID];
__device__ float g_xr2[(size_t)NNODES * HID];
__device__ float g_h2 [(size_t)NNODES * HID];
__device__ int   g_deg[NNODES];
__device__ int   g_cur[NNODES];
__device__ int   g_row[NNODES + 1];
__device__ int   g_src[ETOT];
__device__ float g_pool[NGRAPH * HID];
__device__ float g_cnt[NGRAPH];

// ---------------- init scratch counters ----------------
__global__ void zero_kernel() {
    int i = blockIdx.x * blockDim.x + threadIdx.x;
    if (i < NNODES) { g_deg[i] = 0; g_cur[i] = 0; }
    if (i < NGRAPH * HID) g_pool[i] = 0.f;
    if (i < NGRAPH) g_cnt[i] = 0.f;
}

// ---------------- CSR build: count -> scan -> scatter ----------------
__global__ void count_kernel(const int* __restrict__ ei) {
    int e = blockIdx.x * blockDim.x + threadIdx.x;
    if (e >= ETOT) return;
    int d = (e < NEDGES) ? ei[NEDGES + e] : (e - NEDGES);
    atomicAdd(&g_deg[d], 1);
}

// single-block exclusive scan over NNODES (warp-shuffle based)
__global__ void scan_kernel() {
    __shared__ int warpsum[32];
    __shared__ int carry_sh;
    int tid = threadIdx.x;
    int lane = tid & 31, wid = tid >> 5;
    if (tid == 0) { carry_sh = 0; g_row[0] = 0; }
    __syncthreads();
    for (int base = 0; base < NNODES; base += 1024) {
        int i = base + tid;
        int v = (i < NNODES) ? g_deg[i] : 0;
        #pragma unroll
        for (int off = 1; off < 32; off <<= 1) {
            int t = __shfl_up_sync(0xffffffffu, v, off);
            if (lane >= off) v += t;
        }
        if (lane == 31) warpsum[wid] = v;
        __syncthreads();
        if (wid == 0) {
            int w = warpsum[lane];
            #pragma unroll
            for (int off = 1; off < 32; off <<= 1) {
                int t = __shfl_up_sync(0xffffffffu, w, off);
                if (lane >= off) w += t;
            }
            warpsum[lane] = w;
        }
        __syncthreads();
        int add = carry_sh + (wid > 0 ? warpsum[wid - 1] : 0);
        int incl = v + add;
        if (i < NNODES) g_row[i + 1] = incl;
        __syncthreads();             // everyone has read carry_sh
        if (tid == 1023) carry_sh = incl;
        __syncthreads();
    }
}

__global__ void scatter_kernel(const int* __restrict__ ei) {
    int e = blockIdx.x * blockDim.x + threadIdx.x;
    if (e >= ETOT) return;
    int s, d;
    if (e < NEDGES) { s = ei[e]; d = ei[NEDGES + e]; }
    else            { s = d = e - NEDGES; }
    int pos = atomicAdd(&g_cur[d], 1);
    g_src[g_row[d] + pos] = s;
}

// ---------------- tiled SGEMM: C[N,M] = A[N,K] @ W[K,M] + bias ----------------
// 64 nodes x 64 cols per block, 256 threads, 4x4 microtile.
// layer1 (layer=1): A=x [N,64], gridDim.y=16: y<8 -> W1l/xl1 colblock y,
//                   y>=8 -> W1r/xr1 colblock y-8. M=512.
// layer2 (layer=2): A=g_h1 [N,512], gridDim.y=2: y=0 -> W2l/xl2, y=1 -> W2r/xr2. M=64.
__global__ __launch_bounds__(256) void gemm_kernel(
    int layer, const float* __restrict__ Aext,
    const float* __restrict__ Wl, const float* __restrict__ bl,
    const float* __restrict__ Wr, const float* __restrict__ br)
{
    __shared__ float As[64][68];
    __shared__ float Bs[64][64];

    int K, M, c0;
    const float *A, *W, *bias;
    float* C;
    if (layer == 1) {
        K = FIN; M = D1; A = Aext;
        bool left = blockIdx.y < 8;
        c0 = (left ? blockIdx.y : blockIdx.y - 8) * 64;
        W = left ? Wl : Wr; bias = left ? bl : br;
        C = left ? g_xl1 : g_xr1;
    } else {
        K = D1; M = HID; A = g_h1;
        c0 = 0;
        bool left = blockIdx.y == 0;
        W = left ? Wl : Wr; bias = left ? bl : br;
        C = left ? g_xl2 : g_xr2;
    }

    int tid = threadIdx.x;
    int tx = tid & 15, ty = tid >> 4;
    int n0 = blockIdx.x * 64;

    float acc[4][4];
    {
        float4 bv = *(const float4*)&bias[c0 + tx * 4];
        #pragma unroll
        for (int i = 0; i < 4; i++) {
            acc[i][0] = bv.x; acc[i][1] = bv.y; acc[i][2] = bv.z; acc[i][3] = bv.w;
        }
    }

    for (int k0 = 0; k0 < K; k0 += 64) {
        #pragma unroll
        for (int i = 0; i < 4; i++) {
            int lin = tid + i * 256;
            int r = lin >> 4, cq = lin & 15;
            int gr = n0 + r;
            float4 v = make_float4(0.f, 0.f, 0.f, 0.f);
            if (gr < NNODES) v = *(const float4*)&A[(size_t)gr * K + k0 + cq * 4];
            *(float4*)&As[r][cq * 4] = v;
        }
        #pragma unroll
        for (int i = 0; i < 4; i++) {
            int lin = tid + i * 256;
            int r = lin >> 4, cq = lin & 15;
            *(float4*)&Bs[r][cq * 4] = *(const float4*)&W[(size_t)(k0 + r) * M + c0 + cq * 4];
        }
        __syncthreads();
        #pragma unroll 8
        for (int k = 0; k < 64; k++) {
            float4 bv = *(float4*)&Bs[k][tx * 4];
            float a0 = As[ty * 4 + 0][k];
            float a1 = As[ty * 4 + 1][k];
            float a2 = As[ty * 4 + 2][k];
            float a3 = As[ty * 4 + 3][k];
            acc[0][0] += a0 * bv.x; acc[0][1] += a0 * bv.y; acc[0][2] += a0 * bv.z; acc[0][3] += a0 * bv.w;
            acc[1][0] += a1 * bv.x; acc[1][1] += a1 * bv.y; acc[1][2] += a1 * bv.z; acc[1][3] += a1 * bv.w;
            acc[2][0] += a2 * bv.x; acc[2][1] += a2 * bv.y; acc[2][2] += a2 * bv.z; acc[2][3] += a2 * bv.w;
            acc[3][0] += a3 * bv.x; acc[3][1] += a3 * bv.y; acc[3][2] += a3 * bv.z; acc[3][3] += a3 * bv.w;
        }
        __syncthreads();
    }

    #pragma unroll
    for (int i = 0; i < 4; i++) {
        int gr = n0 + ty * 4 + i;
        if (gr < NNODES)
            *(float4*)&C[(size_t)gr * M + c0 + tx * 4] =
                make_float4(acc[i][0], acc[i][1], acc[i][2], acc[i][3]);
    }
}

// ---------------- GATv2 layer 1: block per node, warp per head, online softmax ----------------
__global__ __launch_bounds__(256) void edge1_kernel(
    const float* __restrict__ att, const float* __restrict__ bias)
{
    __shared__ int ssrc[128];
    int n = blockIdx.x;
    int h = threadIdx.x >> 5;
    int lane = threadIdx.x & 31;
    int c = h * HID + lane * 2;

    float2 av = *(const float2*)&att[c];
    float2 xr = *(const float2*)&g_xr1[(size_t)n * D1 + c];

    int e0 = g_row[n], e1 = g_row[n + 1];
    float m = -3.4e38f, s = 0.f, a0 = 0.f, a1 = 0.f;

    for (int base = e0; base < e1; base += 128) {
        int cnt = min(128, e1 - base);
        __syncthreads();
        for (int i = threadIdx.x; i < cnt; i += 256) ssrc[i] = g_src[base + i];
        __syncthreads();
        for (int t = 0; t < cnt; t++) {
            int src = ssrc[t];
            float2 xl = *(const float2*)&g_xl1[(size_t)src * D1 + c];
            float v0 = xl.x + xr.x; v0 = v0 > 0.f ? v0 : NEG * v0;
            float v1 = xl.y + xr.y; v1 = v1 > 0.f ? v1 : NEG * v1;
            float p = v0 * av.x + v1 * av.y;
            #pragma unroll
            for (int off = 16; off; off >>= 1) p += __shfl_xor_sync(0xffffffffu, p, off);
            float mn = fmaxf(m, p);
            float sc = __expf(m - mn);   // 0 on first edge (m = -inf)
            float w  = __expf(p - mn);
            s  = s  * sc + w;
            a0 = a0 * sc + w * xl.x;
            a1 = a1 * sc + w * xl.y;
            m = mn;
        }
    }
    float inv = 1.f / s;
    float o0 = fmaxf(a0 * inv + bias[c],     0.f);
    float o1 = fmaxf(a1 * inv + bias[c + 1], 0.f);
    *(float2*)&g_h1[(size_t)n * D1 + c] = make_float2(o0, o1);
}

// ---------------- GATv2 layer 2: warp per node (1 head), online softmax ----------------
__global__ __launch_bounds__(256) void edge2_kernel(
    const float* __restrict__ att, const float* __restrict__ bias)
{
    int n = blockIdx.x * 8 + (threadIdx.x >> 5);
    int lane = threadIdx.x & 31;
    int c = lane * 2;

    float2 av = *(const float2*)&att[c];
    float2 xr = *(const float2*)&g_xr2[(size_t)n * HID + c];

    int e0 = g_row[n], e1 = g_row[n + 1];
    float m = -3.4e38f, s = 0.f, a0 = 0.f, a1 = 0.f;

    for (int e = e0; e < e1; e++) {
        int src = g_src[e];
        float2 xl = *(const float2*)&g_xl2[(size_t)src * HID + c];
        float v0 = xl.x + xr.x; v0 = v0 > 0.f ? v0 : NEG * v0;
        float v1 = xl.y + xr.y; v1 = v1 > 0.f ? v1 : NEG * v1;
        float p = v0 * av.x + v1 * av.y;
        #pragma unroll
        for (int off = 16; off; off >>= 1) p += __shfl_xor_sync(0xffffffffu, p, off);
        float mn = fmaxf(m, p);
        float sc = __expf(m - mn);
        float w  = __expf(p - mn);
        s  = s  * sc + w;
        a0 = a0 * sc + w * xl.x;
        a1 = a1 * sc + w * xl.y;
        m = mn;
    }
    float inv = 1.f / s;
    float o0 = a0 * inv + bias[c];       // no ReLU on layer-2 output
    float o1 = a1 * inv + bias[c + 1];
    *(float2*)&g_h2[(size_t)n * HID + c] = make_float2(o0, o1);
}

// ---------------- mean pool by graph ----------------
__global__ void pool_kernel(const int* __restrict__ batch) {
    int idx = blockIdx.x * blockDim.x + threadIdx.x;
    if (idx >= NNODES * HID) return;
    int n = idx >> 6, c = idx & 63;
    int g = batch[n];
    atomicAdd(&g_pool[g * HID + c], g_h2[idx]);
    if (c == 0) atomicAdd(&g_cnt[g], 1.f);
}

// ---------------- MLP head: one block per graph ----------------
__global__ void head_kernel(const float* __restrict__ gf,
                            const float* __restrict__ w1, const float* __restrict__ b1,
                            const float* __restrict__ w2, const float* __restrict__ b2,
                            float* __restrict__ out)
{
    int g = blockIdx.x;
    int j = threadIdx.x;
    __shared__ float pl[HID];
    __shared__ float z[HID];

    float cm = fmaxf(g_cnt[g], 1.f);
    pl[j] = g_pool[g * HID + j] / cm;
    __syncthreads();

    float acc = b1[j];
    #pragma unroll 8
    for (int k = 0; k < HID; k++)   acc += pl[k] * w1[k * HID + j];
    #pragma unroll
    for (int k = 0; k < GFEAT; k++) acc += gf[g * GFEAT + k] * w1[(HID + k) * HID + j];
    z[j] = fmaxf(acc, 0.f);
    __syncthreads();

    if (j < NCLS) {
        float o = b2[j];
        #pragma unroll 8
        for (int k = 0; k < HID; k++) o += z[k] * w2[k * NCLS + j];
        out[g * NCLS + j] = o;
    }
}

// ---------------- launcher ----------------
extern "C" void kernel_launch(void* const* d_in, const int* in_sizes, int n_in,
                              void* d_out, int out_size)
{
    const float* x     = (const float*)d_in[0];
    const int*   ei    = (const int*)  d_in[1];
    const int*   batch = (const int*)  d_in[2];
    const float* gf    = (const float*)d_in[3];
    const float* W1l   = (const float*)d_in[4];
    const float* b1l   = (const float*)d_in[5];
    const float* W1r   = (const float*)d_in[6];
    const float* b1r   = (const float*)d_in[7];
    const float* att1  = (const float*)d_in[8];
    const float* bias1 = (const float*)d_in[9];
    const float* W2l   = (const float*)d_in[10];
    const float* b2l   = (const float*)d_in[11];
    const float* W2r   = (const float*)d_in[12];
    const float* b2r   = (const float*)d_in[13];
    const float* att2  = (const float*)d_in[14];
    const float* bias2 = (const float*)d_in[15];
    const float* l1W   = (const float*)d_in[16];
    const float* l1b   = (const float*)d_in[17];
    const float* l2W   = (const float*)d_in[18];
    const float* l2b   = (const float*)d_in[19];
    float* out = (float*)d_out;

    const int NB = (NNODES + 63) / 64;   // 313

    zero_kernel   <<<(NNODES + 255) / 256, 256>>>();
    count_kernel  <<<(ETOT + 255) / 256, 256>>>(ei);
    scan_kernel   <<<1, 1024>>>();
    scatter_kernel<<<(ETOT + 255) / 256, 256>>>(ei);

    // layer-1 projections (fused xl1 + xr1 in one launch)
    gemm_kernel<<<dim3(NB, 16), 256>>>(1, x, W1l, b1l, W1r, b1r);
    edge1_kernel<<<NNODES, 256>>>(att1, bias1);

    // layer-2 projections (fused xl2 + xr2 in one launch)
    gemm_kernel<<<dim3(NB, 2), 256>>>(2, nullptr, W2l, b2l, W2r, b2r);
    edge2_kernel<<<NNODES / 8, 256>>>(att2, bias2);

    pool_kernel<<<(NNODES * HID + 255) / 256, 256>>>(batch);
    head_kernel<<<NGRAPH, HID>>>(gf, l1W, l1b, l2W, l2b, out);
}

// round 3
// speedup vs baseline: 1.1063x; 1.1063x over previous
#include <cuda_runtime.h>

// ---------------- problem constants (fixed-shape problem) ----------------
#define NNODES 20000
#define NEDGES 320000
#define ETOT   (NEDGES + NNODES)
#define NGRAPH 64
#define FIN    64
#define HID    64
#define NHEAD  8
#define GFEAT  16
#define NCLS   10
#define NEG    0.2f
#define D1     (NHEAD * HID)   // 512

// ---------------- device scratch (static, no allocation) ----------------
__device__ float g_xl1[(size_t)NNODES * D1];
__device__ float g_xr1[(size_t)NNODES * D1];
__device__ float g_h1 [(size_t)NNODES * D1];
__device__ float g_xl2[(size_t)NNODES * HID];
__device__ float g_xr2[(size_t)NNODES * HID];
__device__ int   g_deg[NNODES];
__device__ int   g_cur[NNODES];
__device__ int   g_row[NNODES + 1];
__device__ int   g_src[ETOT];
__device__ int   g_bsum[32];
__device__ int   g_boff[32];
__device__ float g_pool[NGRAPH * HID];
__device__ float g_cnt[NGRAPH];

// ---------------- init scratch counters ----------------
__global__ void zero_kernel() {
    int i = blockIdx.x * blockDim.x + threadIdx.x;
    if (i < NNODES) { g_deg[i] = 0; g_cur[i] = 0; }
    if (i < NGRAPH * HID) g_pool[i] = 0.f;
    if (i < NGRAPH) g_cnt[i] = 0.f;
}

// ---------------- CSR build: count -> 3-stage scan -> scatter ----------------
__global__ void count_kernel(const int* __restrict__ ei) {
    int e = blockIdx.x * blockDim.x + threadIdx.x;
    if (e >= ETOT) return;
    int d = (e < NEDGES) ? ei[NEDGES + e] : (e - NEDGES);
    atomicAdd(&g_deg[d], 1);
}

// stage 1: per-block inclusive scan of 1024 degrees -> g_row[i+1] (partial), block sum
__global__ void scan_block_kernel() {
    __shared__ int warpsum[32];
    int tid = threadIdx.x;
    int lane = tid & 31, wid = tid >> 5;
    int i = blockIdx.x * 1024 + tid;
    int v = (i < NNODES) ? g_deg[i] : 0;
    #pragma unroll
    for (int off = 1; off < 32; off <<= 1) {
        int t = __shfl_up_sync(0xffffffffu, v, off);
        if (lane >= off) v += t;
    }
    if (lane == 31) warpsum[wid] = v;
    __syncthreads();
    if (wid == 0) {
        int w = warpsum[lane];
        #pragma unroll
        for (int off = 1; off < 32; off <<= 1) {
            int t = __shfl_up_sync(0xffffffffu, w, off);
            if (lane >= off) w += t;
        }
        warpsum[lane] = w;
    }
    __syncthreads();
    int incl = v + (wid > 0 ? warpsum[wid - 1] : 0);
    if (i < NNODES) g_row[i + 1] = incl;
    if (tid == 1023) g_bsum[blockIdx.x] = incl;
}

// stage 2: exclusive scan over the (<=32) block sums
__global__ void scan_top_kernel(int nblk) {
    int lane = threadIdx.x;
    int v = (lane < nblk) ? g_bsum[lane] : 0;
    int s = 0;
    #pragma unroll
    for (int off = 1; off < 32; off <<= 1) {
        int t = __shfl_up_sync(0xffffffffu, v, off);
        if (lane >= off) v += t;
    }
    s = v - ((lane < nblk) ? g_bsum[lane] : 0);   // exclusive
    if (lane < nblk) g_boff[lane] = s;
    if (lane == 0) g_row[0] = 0;
}

// stage 3: add block offsets
__global__ void scan_add_kernel() {
    int i = blockIdx.x * 1024 + threadIdx.x;
    if (i < NNODES) g_row[i + 1] += g_boff[blockIdx.x];
}

__global__ void scatter_kernel(const int* __restrict__ ei) {
    int e = blockIdx.x * blockDim.x + threadIdx.x;
    if (e >= ETOT) return;
    int s, d;
    if (e < NEDGES) { s = ei[e]; d = ei[NEDGES + e]; }
    else            { s = d = e - NEDGES; }
    int pos = atomicAdd(&g_cur[d], 1);
    g_src[g_row[d] + pos] = s;
}

// ---------------- SGEMM: virtual-M fused L/R projection ----------------
// C[N, 2*Mreal] = A[N,K] @ [Wl | Wr] + [bl | br], 128x128 tile, 8x8 microtile.
// layer==1: A=Aext (x), K=64,  Mreal=512, Cl=g_xl1, Cr=g_xr1, gridDim.y=8
// layer==2: A=g_h1,    K=512, Mreal=64,  Cl=g_xl2, Cr=g_xr2, gridDim.y=1
__global__ __launch_bounds__(256, 2) void gemm_kernel(
    int layer, const float* __restrict__ Aext,
    const float* __restrict__ Wl, const float* __restrict__ bl,
    const float* __restrict__ Wr, const float* __restrict__ br)
{
    __shared__ float As[128][36];   // [m][k-panel 32 + pad]
    __shared__ float Bs[32][132];   // [k][n 128 + pad]

    int K, Mreal;
    const float* A;
    if (layer == 1) { K = FIN; Mreal = D1; A = Aext; }
    else            { K = D1;  Mreal = HID; A = g_h1; }

    int tid = threadIdx.x;
    int tx = tid & 15, ty = tid >> 4;
    int n0 = blockIdx.x * 128;
    int vc0 = blockIdx.y * 128 + tx * 8;   // virtual col of this thread's 8 cols
    bool left = vc0 < Mreal;
    int  mcol = left ? vc0 : vc0 - Mreal;
    const float* Wm = left ? Wl : Wr;
    const float* bm = left ? bl : br;
    float* C;
    if (layer == 1) C = left ? g_xl1 : g_xr1;
    else            C = left ? g_xl2 : g_xr2;

    float acc[8][8];
    {
        float4 bv0 = *(const float4*)&bm[mcol];
        float4 bv1 = *(const float4*)&bm[mcol + 4];
        #pragma unroll
        for (int i = 0; i < 8; i++) {
            acc[i][0] = bv0.x; acc[i][1] = bv0.y; acc[i][2] = bv0.z; acc[i][3] = bv0.w;
            acc[i][4] = bv1.x; acc[i][5] = bv1.y; acc[i][6] = bv1.z; acc[i][7] = bv1.w;
        }
    }

    for (int k0 = 0; k0 < K; k0 += 32) {
        // load A tile: 128 rows x 32 k -> As[m][k]
        #pragma unroll
        for (int i = 0; i < 4; i++) {
            int lin = tid + i * 256;
            int r = lin >> 3, kq = (lin & 7) * 4;
            int gr = n0 + r;
            float4 v = make_float4(0.f, 0.f, 0.f, 0.f);
            if (gr < NNODES) v = *(const float4*)&A[(size_t)gr * K + k0 + kq];
            *(float4*)&As[r][kq] = v;
        }
        // load B tile: 32 k x 128 virtual cols -> Bs[k][n]
        #pragma unroll
        for (int i = 0; i < 4; i++) {
            int lin = tid + i * 256;
            int k = lin >> 5, nq = (lin & 31) * 4;
            int vc = blockIdx.y * 128 + nq;
            bool bleft = vc < Mreal;
            int col = bleft ? vc : vc - Mreal;
            const float* W = bleft ? Wl : Wr;
            *(float4*)&Bs[k][nq] = *(const float4*)&W[(size_t)(k0 + k) * Mreal + col];
        }
        __syncthreads();
        #pragma unroll
        for (int k = 0; k < 32; k++) {
            float a[8], b[8];
            #pragma unroll
            for (int i = 0; i < 8; i++) a[i] = As[ty * 8 + i][k];
            *(float4*)&b[0] = *(float4*)&Bs[k][tx * 8];
            *(float4*)&b[4] = *(float4*)&Bs[k][tx * 8 + 4];
            #pragma unroll
            for (int i = 0; i < 8; i++)
                #pragma unroll
                for (int j = 0; j < 8; j++)
                    acc[i][j] += a[i] * b[j];
        }
        __syncthreads();
    }

    #pragma unroll
    for (int i = 0; i < 8; i++) {
        int gr = n0 + ty * 8 + i;
        if (gr < NNODES) {
            *(float4*)&C[(size_t)gr * Mreal + mcol]     = *(float4*)&acc[i][0];
            *(float4*)&C[(size_t)gr * Mreal + mcol + 4] = *(float4*)&acc[i][4];
        }
    }
    (void)Wm;
}

// ---------------- GATv2 layer 1: 2 warps/node, 4 heads/warp, 8 ch/lane ----------------
__global__ __launch_bounds__(256) void edge1_kernel(
    const float* __restrict__ att, const float* __restrict__ bias)
{
    int warp = threadIdx.x >> 5;                 // 0..7
    int n = blockIdx.x * 4 + (warp >> 1);
    int wp = warp & 1;                           // head half (heads 0-3 or 4-7)
    int lane = threadIdx.x & 31;
    int coff = wp * 256 + (lane >> 3) * 64 + (lane & 7) * 8;

    float4 av0 = *(const float4*)&att[coff];
    float4 av1 = *(const float4*)&att[coff + 4];
    float4 xr0 = *(const float4*)&g_xr1[(size_t)n * D1 + coff];
    float4 xr1 = *(const float4*)&g_xr1[(size_t)n * D1 + coff + 4];

    int e0 = g_row[n], e1 = g_row[n + 1];
    float m = -3.4e38f, s = 0.f;
    float acc[8];
    #pragma unroll
    for (int i = 0; i < 8; i++) acc[i] = 0.f;

    const float4* xlv = (const float4*)g_xl1;
    int cq = coff >> 2;

    // software pipeline: prefetch xl row of next edge
    int src = g_src[e0];
    float4 a0 = xlv[(size_t)src * 128 + cq];
    float4 a1 = xlv[(size_t)src * 128 + cq + 1];

    for (int e = e0; e < e1; e++) {
        float4 b0 = a0, b1 = a1;
        if (e + 1 < e1) {
            int ns = g_src[e + 1];
            a0 = xlv[(size_t)ns * 128 + cq];
            a1 = xlv[(size_t)ns * 128 + cq + 1];
        }
        // leaky_relu(xl + xr) dot att  (leaky(x) = max(x, 0.2x))
        float p;
        {
            float v, l;
            v = b0.x + xr0.x; l = fmaxf(v, NEG * v); p  = l * av0.x;
            v = b0.y + xr0.y; l = fmaxf(v, NEG * v); p += l * av0.y;
            v = b0.z + xr0.z; l = fmaxf(v, NEG * v); p += l * av0.z;
            v = b0.w + xr0.w; l = fmaxf(v, NEG * v); p += l * av0.w;
            v = b1.x + xr1.x; l = fmaxf(v, NEG * v); p += l * av1.x;
            v = b1.y + xr1.y; l = fmaxf(v, NEG * v); p += l * av1.y;
            v = b1.z + xr1.z; l = fmaxf(v, NEG * v); p += l * av1.z;
            v = b1.w + xr1.w; l = fmaxf(v, NEG * v); p += l * av1.w;
        }
        // reduce within 8-lane head segment
        p += __shfl_xor_sync(0xffffffffu, p, 1);
        p += __shfl_xor_sync(0xffffffffu, p, 2);
        p += __shfl_xor_sync(0xffffffffu, p, 4);

        float mn = fmaxf(m, p);
        float sc = __expf(m - mn);
        float w  = __expf(p - mn);
        s = s * sc + w;
        acc[0] = acc[0] * sc + w * b0.x;
        acc[1] = acc[1] * sc + w * b0.y;
        acc[2] = acc[2] * sc + w * b0.z;
        acc[3] = acc[3] * sc + w * b0.w;
        acc[4] = acc[4] * sc + w * b1.x;
        acc[5] = acc[5] * sc + w * b1.y;
        acc[6] = acc[6] * sc + w * b1.z;
        acc[7] = acc[7] * sc + w * b1.w;
        m = mn;
    }

    float inv = 1.f / s;
    float4 o0, o1;
    o0.x = fmaxf(acc[0] * inv + bias[coff + 0], 0.f);
    o0.y = fmaxf(acc[1] * inv + bias[coff + 1], 0.f);
    o0.z = fmaxf(acc[2] * inv + bias[coff + 2], 0.f);
    o0.w = fmaxf(acc[3] * inv + bias[coff + 3], 0.f);
    o1.x = fmaxf(acc[4] * inv + bias[coff + 4], 0.f);
    o1.y = fmaxf(acc[5] * inv + bias[coff + 5], 0.f);
    o1.z = fmaxf(acc[6] * inv + bias[coff + 6], 0.f);
    o1.w = fmaxf(acc[7] * inv + bias[coff + 7], 0.f);
    *(float4*)&g_h1[(size_t)n * D1 + coff]     = o0;
    *(float4*)&g_h1[(size_t)n * D1 + coff + 4] = o1;
}

// ---------------- GATv2 layer 2 (1 head) + fused mean-pool accumulation ----------------
__global__ __launch_bounds__(256) void edge2_kernel(
    const float* __restrict__ att, const float* __restrict__ bias,
    const int* __restrict__ batch)
{
    int n = blockIdx.x * 8 + (threadIdx.x >> 5);
    int lane = threadIdx.x & 31;
    int c = lane * 2;

    float2 av = *(const float2*)&att[c];
    float2 xr = *(const float2*)&g_xr2[(size_t)n * HID + c];

    int e0 = g_row[n], e1 = g_row[n + 1];
    float m = -3.4e38f, s = 0.f, a0 = 0.f, a1 = 0.f;

    int src = g_src[e0];
    float2 xl = *(const float2*)&g_xl2[(size_t)src * HID + c];

    for (int e = e0; e < e1; e++) {
        float2 b = xl;
        if (e + 1 < e1) {
            int ns = g_src[e + 1];
            xl = *(const float2*)&g_xl2[(size_t)ns * HID + c];
        }
        float v0 = b.x + xr.x; v0 = fmaxf(v0, NEG * v0);
        float v1 = b.y + xr.y; v1 = fmaxf(v1, NEG * v1);
        float p = v0 * av.x + v1 * av.y;
        #pragma unroll
        for (int off = 16; off; off >>= 1) p += __shfl_xor_sync(0xffffffffu, p, off);
        float mn = fmaxf(m, p);
        float sc = __expf(m - mn);
        float w  = __expf(p - mn);
        s  = s  * sc + w;
        a0 = a0 * sc + w * b.x;
        a1 = a1 * sc + w * b.y;
        m = mn;
    }
    float inv = 1.f / s;
    float o0 = a0 * inv + bias[c];
    float o1 = a1 * inv + bias[c + 1];

    int g = batch[n];
    atomicAdd(&g_pool[g * HID + c],     o0);
    atomicAdd(&g_pool[g * HID + c + 1], o1);
    if (lane == 0) atomicAdd(&g_cnt[g], 1.f);
}

// ---------------- MLP head: one block per graph ----------------
__global__ void head_kernel(const float* __restrict__ gf,
                            const float* __restrict__ w1, const float* __restrict__ b1,
                            const float* __restrict__ w2, const float* __restrict__ b2,
                            float* __restrict__ out)
{
    int g = blockIdx.x;
    int j = threadIdx.x;
    __shared__ float pl[HID];
    __shared__ float z[HID];

    float cm = fmaxf(g_cnt[g], 1.f);
    pl[j] = g_pool[g * HID + j] / cm;
    __syncthreads();

    float acc = b1[j];
    #pragma unroll 8
    for (int k = 0; k < HID; k++)   acc += pl[k] * w1[k * HID + j];
    #pragma unroll
    for (int k = 0; k < GFEAT; k++) acc += gf[g * GFEAT + k] * w1[(HID + k) * HID + j];
    z[j] = fmaxf(acc, 0.f);
    __syncthreads();

    if (j < NCLS) {
        float o = b2[j];
        #pragma unroll 8
        for (int k = 0; k < HID; k++) o += z[k] * w2[k * NCLS + j];
        out[g * NCLS + j] = o;
    }
}

// ---------------- launcher ----------------
extern "C" void kernel_launch(void* const* d_in, const int* in_sizes, int n_in,
                              void* d_out, int out_size)
{
    const float* x     = (const float*)d_in[0];
    const int*   ei    = (const int*)  d_in[1];
    const int*   batch = (const int*)  d_in[2];
    const float* gf    = (const float*)d_in[3];
    const float* W1l   = (const float*)d_in[4];
    const float* b1l   = (const float*)d_in[5];
    const float* W1r   = (const float*)d_in[6];
    const float* b1r   = (const float*)d_in[7];
    const float* att1  = (const float*)d_in[8];
    const float* bias1 = (const float*)d_in[9];
    const float* W2l   = (const float*)d_in[10];
    const float* b2l   = (const float*)d_in[11];
    const float* W2r   = (const float*)d_in[12];
    const float* b2r   = (const float*)d_in[13];
    const float* att2  = (const float*)d_in[14];
    const float* bias2 = (const float*)d_in[15];
    const float* l1W   = (const float*)d_in[16];
    const float* l1b   = (const float*)d_in[17];
    const float* l2W   = (const float*)d_in[18];
    const float* l2b   = (const float*)d_in[19];
    float* out = (float*)d_out;

    const int NSCAN = (NNODES + 1023) / 1024;   // 20
    const int NBG   = (NNODES + 127) / 128;     // 157

    zero_kernel      <<<(NNODES + 255) / 256, 256>>>();
    count_kernel     <<<(ETOT + 255) / 256, 256>>>(ei);
    scan_block_kernel<<<NSCAN, 1024>>>();
    scan_top_kernel  <<<1, 32>>>(NSCAN);
    scan_add_kernel  <<<NSCAN, 1024>>>();
    scatter_kernel   <<<(ETOT + 255) / 256, 256>>>(ei);

    gemm_kernel<<<dim3(NBG, 8), 256>>>(1, x, W1l, b1l, W1r, b1r);
    edge1_kernel<<<NNODES / 4, 256>>>(att1, bias1);

    gemm_kernel<<<dim3(NBG, 1), 256>>>(2, nullptr, W2l, b2l, W2r, b2r);
    edge2_kernel<<<NNODES / 8, 256>>>(att2, bias2, batch);

    head_kernel<<<NGRAPH, HID>>>(gf, l1W, l1b, l2W, l2b, out);
}

// round 11
// speedup vs baseline: 1.7401x; 1.5730x over previous
#include <cuda_runtime.h>
#include <cstdint>

// ---------------- problem constants (fixed-shape problem) ----------------
#define NNODES 20000
#define NEDGES 320000
#define ETOT   (NEDGES + NNODES)
#define NGRAPH 64
#define FIN    64
#define HID    64
#define NHEAD  8
#define GFEAT  16
#define NCLS   10
#define NEG    0.2f
#define D1     (NHEAD * HID)   // 512

// ---------------- device scratch (static, no allocation) ----------------
__device__ float g_xl1[(size_t)NNODES * D1];
__device__ float g_xr1[(size_t)NNODES * D1];
__device__ float g_h1 [(size_t)NNODES * D1];
__device__ float g_xl2[(size_t)NNODES * HID];
__device__ float g_xr2[(size_t)NNODES * HID];
__device__ int   g_deg[NNODES];
__device__ int   g_cur[NNODES];
__device__ int   g_row[NNODES + 1];
__device__ int   g_src[ETOT];
__device__ int   g_bsum[32];
__device__ int   g_boff[32];
__device__ float g_pool[NGRAPH * HID];
__device__ float g_cnt[NGRAPH];

// ---------------- init scratch counters ----------------
__global__ void zero_kernel() {
    int i = blockIdx.x * blockDim.x + threadIdx.x;
    if (i < NNODES) { g_deg[i] = 0; g_cur[i] = 0; }
    if (i < NGRAPH * HID) g_pool[i] = 0.f;
    if (i < NGRAPH) g_cnt[i] = 0.f;
}

// ---------------- CSR build: count -> 3-stage scan -> scatter ----------------
__global__ void count_kernel(const int* __restrict__ ei) {
    int e = blockIdx.x * blockDim.x + threadIdx.x;
    if (e >= ETOT) return;
    int d = (e < NEDGES) ? ei[NEDGES + e] : (e - NEDGES);
    atomicAdd(&g_deg[d], 1);
}

__global__ void scan_block_kernel() {
    __shared__ int warpsum[32];
    int tid = threadIdx.x;
    int lane = tid & 31, wid = tid >> 5;
    int i = blockIdx.x * 1024 + tid;
    int v = (i < NNODES) ? g_deg[i] : 0;
    #pragma unroll
    for (int off = 1; off < 32; off <<= 1) {
        int t = __shfl_up_sync(0xffffffffu, v, off);
        if (lane >= off) v += t;
    }
    if (lane == 31) warpsum[wid] = v;
    __syncthreads();
    if (wid == 0) {
        int w = warpsum[lane];
        #pragma unroll
        for (int off = 1; off < 32; off <<= 1) {
            int t = __shfl_up_sync(0xffffffffu, w, off);
            if (lane >= off) w += t;
        }
        warpsum[lane] = w;
    }
    __syncthreads();
    int incl = v + (wid > 0 ? warpsum[wid - 1] : 0);
    if (i < NNODES) g_row[i + 1] = incl;
    if (tid == 1023) g_bsum[blockIdx.x] = incl;
}

__global__ void scan_top_kernel(int nblk) {
    int lane = threadIdx.x;
    int orig = (lane < nblk) ? g_bsum[lane] : 0;
    int v = orig;
    #pragma unroll
    for (int off = 1; off < 32; off <<= 1) {
        int t = __shfl_up_sync(0xffffffffu, v, off);
        if (lane >= off) v += t;
    }
    if (lane < nblk) g_boff[lane] = v - orig;
    if (lane == 0) g_row[0] = 0;
}

__global__ void scan_add_kernel() {
    int i = blockIdx.x * 1024 + threadIdx.x;
    if (i < NNODES) g_row[i + 1] += g_boff[blockIdx.x];
}

__global__ void scatter_kernel(const int* __restrict__ ei) {
    int e = blockIdx.x * blockDim.x + threadIdx.x;
    if (e >= ETOT) return;
    int s, d;
    if (e < NEDGES) { s = ei[e]; d = ei[NEDGES + e]; }
    else            { s = d = e - NEDGES; }
    int pos = atomicAdd(&g_cur[d], 1);
    g_src[g_row[d] + pos] = s;
}

// ---------------- tf32 tensor-core GEMM, virtual-M fused L/R projection ----------------
// C[N, 2*Mreal] = A[N,K] @ [Wl | Wr] + [bl | br]
// 128x128 block tile, BK=32, 256 threads = 8 warps (2m x 4n), 64x32 warp tile,
// mma.sync m16n8k8 tf32, fp32 accumulate, fp32 bias epilogue.
__device__ __forceinline__ uint32_t f2tf(float f) {
    uint32_t r; asm("cvt.rna.tf32.f32 %0, %1;" : "=r"(r) : "f"(f)); return r;
}
__device__ __forceinline__ void mma_tf32(float c[4],
    uint32_t a0, uint32_t a1, uint32_t a2, uint32_t a3, uint32_t b0, uint32_t b1)
{
    asm volatile(
        "mma.sync.aligned.m16n8k8.row.col.f32.tf32.tf32.f32 "
        "{%0,%1,%2,%3}, {%4,%5,%6,%7}, {%8,%9}, {%0,%1,%2,%3};"
        : "+f"(c[0]), "+f"(c[1]), "+f"(c[2]), "+f"(c[3])
        : "r"(a0), "r"(a1), "r"(a2), "r"(a3), "r"(b0), "r"(b1));
}

__global__ __launch_bounds__(256, 2) void gemm_tc_kernel(
    int layer, const float* __restrict__ Aext,
    const float* __restrict__ Wl, const float* __restrict__ bl,
    const float* __restrict__ Wr, const float* __restrict__ br)
{
    __shared__ uint32_t As[128][36];   // [m][k], pad 36 -> conflict-free frag loads
    __shared__ uint32_t Bs[32][136];   // [k][n], pad 136 (tig*8 bank spread)

    int K, Mreal;
    const float* A;
    if (layer == 1) { K = FIN; Mreal = D1;  A = Aext; }
    else            { K = D1;  Mreal = HID; A = g_h1; }

    int tid = threadIdx.x;
    int wid = tid >> 5, lane = tid & 31;
    int wm = (wid >> 2) * 64;          // warp m offset in tile
    int wn = (wid & 3) * 32;           // warp n offset in tile
    int grp = lane >> 2, tig = lane & 3;
    int n0 = blockIdx.x * 128;

    float acc[4][4][4];                // [mfrag][nfrag][reg]
    #pragma unroll
    for (int i = 0; i < 4; i++)
        #pragma unroll
        for (int j = 0; j < 4; j++)
            #pragma unroll
            for (int r = 0; r < 4; r++) acc[i][j][r] = 0.f;

    for (int k0 = 0; k0 < K; k0 += 32) {
        // A tile: 128 x 32
        #pragma unroll
        for (int i = 0; i < 4; i++) {
            int lin = tid + i * 256;
            int r = lin >> 3, kq = (lin & 7) * 4;
            int gr = n0 + r;
            float4 v = make_float4(0.f, 0.f, 0.f, 0.f);
            if (gr < NNODES) v = *(const float4*)&A[(size_t)gr * K + k0 + kq];
            As[r][kq + 0] = f2tf(v.x); As[r][kq + 1] = f2tf(v.y);
            As[r][kq + 2] = f2tf(v.z); As[r][kq + 3] = f2tf(v.w);
        }
        // B tile: 32 k x 128 virtual cols
        #pragma unroll
        for (int i = 0; i < 4; i++) {
            int lin = tid + i * 256;
            int k = lin >> 5, nq = (lin & 31) * 4;
            int vc = blockIdx.y * 128 + nq;
            bool bleft = vc < Mreal;
            int col = bleft ? vc : vc - Mreal;
            const float* W = bleft ? Wl : Wr;
            float4 v = *(const float4*)&W[(size_t)(k0 + k) * Mreal + col];
            Bs[k][nq + 0] = f2tf(v.x); Bs[k][nq + 1] = f2tf(v.y);
            Bs[k][nq + 2] = f2tf(v.z); Bs[k][nq + 3] = f2tf(v.w);
        }
        __syncthreads();

        #pragma unroll
        for (int ks = 0; ks < 4; ks++) {
            int kk = ks * 8;
            uint32_t af[4][4];
            #pragma unroll
            for (int mf = 0; mf < 4; mf++) {
                int row = wm + mf * 16 + grp;
                af[mf][0] = As[row][kk + tig];
                af[mf][1] = As[row + 8][kk + tig];
                af[mf][2] = As[row][kk + tig + 4];
                af[mf][3] = As[row + 8][kk + tig + 4];
            }
            #pragma unroll
            for (int nf = 0; nf < 4; nf++) {
                int col = wn + nf * 8 + grp;
                uint32_t b0 = Bs[kk + tig][col];
                uint32_t b1 = Bs[kk + tig + 4][col];
                #pragma unroll
                for (int mf = 0; mf < 4; mf++)
                    mma_tf32(acc[mf][nf], af[mf][0], af[mf][1], af[mf][2], af[mf][3], b0, b1);
            }
        }
        __syncthreads();
    }

    // epilogue: bias + store (columns vc, vc+1 contiguous -> float2)
    #pragma unroll
    for (int nf = 0; nf < 4; nf++) {
        int vc = blockIdx.y * 128 + wn + nf * 8 + tig * 2;
        bool left = vc < Mreal;
        int col = left ? vc : vc - Mreal;
        const float* bm = left ? bl : br;
        float* C;
        if (layer == 1) C = left ? g_xl1 : g_xr1;
        else            C = left ? g_xl2 : g_xr2;
        float2 bv = *(const float2*)&bm[col];
        #pragma unroll
        for (int mf = 0; mf < 4; mf++) {
            int r0 = n0 + wm + mf * 16 + grp;
            if (r0 < NNODES)
                *(float2*)&C[(size_t)r0 * Mreal + col] =
                    make_float2(acc[mf][nf][0] + bv.x, acc[mf][nf][1] + bv.y);
            int r1 = r0 + 8;
            if (r1 < NNODES)
                *(float2*)&C[(size_t)r1 * Mreal + col] =
                    make_float2(acc[mf][nf][2] + bv.x, acc[mf][nf][3] + bv.y);
        }
    }
}

// ---------------- GATv2 layer 1: 2 warps/node, 4 heads/warp, 8 ch/lane ----------------
__global__ __launch_bounds__(256) void edge1_kernel(
    const float* __restrict__ att, const float* __restrict__ bias)
{
    int warp = threadIdx.x >> 5;
    int n = blockIdx.x * 4 + (warp >> 1);
    int wp = warp & 1;
    int lane = threadIdx.x & 31;
    int coff = wp * 256 + (lane >> 3) * 64 + (lane & 7) * 8;

    float4 av0 = *(const float4*)&att[coff];
    float4 av1 = *(const float4*)&att[coff + 4];
    float4 xr0 = *(const float4*)&g_xr1[(size_t)n * D1 + coff];
    float4 xr1 = *(const float4*)&g_xr1[(size_t)n * D1 + coff + 4];

    int e0 = g_row[n], e1 = g_row[n + 1];
    float m = -3.4e38f, s = 0.f;
    float acc[8];
    #pragma unroll
    for (int i = 0; i < 8; i++) acc[i] = 0.f;

    const float4* xlv = (const float4*)g_xl1;
    int cq = coff >> 2;

    int src = g_src[e0];
    float4 a0 = xlv[(size_t)src * 128 + cq];
    float4 a1 = xlv[(size_t)src * 128 + cq + 1];

    for (int e = e0; e < e1; e++) {
        float4 b0 = a0, b1 = a1;
        if (e + 1 < e1) {
            int ns = g_src[e + 1];
            a0 = xlv[(size_t)ns * 128 + cq];
            a1 = xlv[(size_t)ns * 128 + cq + 1];
        }
        float p;
        {
            float v, l;
            v = b0.x + xr0.x; l = fmaxf(v, NEG * v); p  = l * av0.x;
            v = b0.y + xr0.y; l = fmaxf(v, NEG * v); p += l * av0.y;
            v = b0.z + xr0.z; l = fmaxf(v, NEG * v); p += l * av0.z;
            v = b0.w + xr0.w; l = fmaxf(v, NEG * v); p += l * av0.w;
            v = b1.x + xr1.x; l = fmaxf(v, NEG * v); p += l * av1.x;
            v = b1.y + xr1.y; l = fmaxf(v, NEG * v); p += l * av1.y;
            v = b1.z + xr1.z; l = fmaxf(v, NEG * v); p += l * av1.z;
            v = b1.w + xr1.w; l = fmaxf(v, NEG * v); p += l * av1.w;
        }
        p += __shfl_xor_sync(0xffffffffu, p, 1);
        p += __shfl_xor_sync(0xffffffffu, p, 2);
        p += __shfl_xor_sync(0xffffffffu, p, 4);

        float mn = fmaxf(m, p);
        float sc = __expf(m - mn);
        float w  = __expf(p - mn);
        s = s * sc + w;
        acc[0] = acc[0] * sc + w * b0.x;
        acc[1] = acc[1] * sc + w * b0.y;
        acc[2] = acc[2] * sc + w * b0.z;
        acc[3] = acc[3] * sc + w * b0.w;
        acc[4] = acc[4] * sc + w * b1.x;
        acc[5] = acc[5] * sc + w * b1.y;
        acc[6] = acc[6] * sc + w * b1.z;
        acc[7] = acc[7] * sc + w * b1.w;
        m = mn;
    }

    float inv = 1.f / s;
    float4 o0, o1;
    o0.x = fmaxf(acc[0] * inv + bias[coff + 0], 0.f);
    o0.y = fmaxf(acc[1] * inv + bias[coff + 1], 0.f);
    o0.z = fmaxf(acc[2] * inv + bias[coff + 2], 0.f);
    o0.w = fmaxf(acc[3] * inv + bias[coff + 3], 0.f);
    o1.x = fmaxf(acc[4] * inv + bias[coff + 4], 0.f);
    o1.y = fmaxf(acc[5] * inv + bias[coff + 5], 0.f);
    o1.z = fmaxf(acc[6] * inv + bias[coff + 6], 0.f);
    o1.w = fmaxf(acc[7] * inv + bias[coff + 7], 0.f);
    *(float4*)&g_h1[(size_t)n * D1 + coff]     = o0;
    *(float4*)&g_h1[(size_t)n * D1 + coff + 4] = o1;
}

// ---------------- GATv2 layer 2 (1 head) + fused mean-pool accumulation ----------------
__global__ __launch_bounds__(256) void edge2_kernel(
    const float* __restrict__ att, const float* __restrict__ bias,
    const int* __restrict__ batch)
{
    int n = blockIdx.x * 8 + (threadIdx.x >> 5);
    int lane = threadIdx.x & 31;
    int c = lane * 2;

    float2 av = *(const float2*)&att[c];
    float2 xr = *(const float2*)&g_xr2[(size_t)n * HID + c];

    int e0 = g_row[n], e1 = g_row[n + 1];
    float m = -3.4e38f, s = 0.f, a0 = 0.f, a1 = 0.f;

    int src = g_src[e0];
    float2 xl = *(const float2*)&g_xl2[(size_t)src * HID + c];

    for (int e = e0; e < e1; e++) {
        float2 b = xl;
        if (e + 1 < e1) {
            int ns = g_src[e + 1];
            xl = *(const float2*)&g_xl2[(size_t)ns * HID + c];
        }
        float v0 = b.x + xr.x; v0 = fmaxf(v0, NEG * v0);
        float v1 = b.y + xr.y; v1 = fmaxf(v1, NEG * v1);
        float p = v0 * av.x + v1 * av.y;
        #pragma unroll
        for (int off = 16; off; off >>= 1) p += __shfl_xor_sync(0xffffffffu, p, off);
        float mn = fmaxf(m, p);
        float sc = __expf(m - mn);
        float w  = __expf(p - mn);
        s  = s  * sc + w;
        a0 = a0 * sc + w * b.x;
        a1 = a1 * sc + w * b.y;
        m = mn;
    }
    float inv = 1.f / s;
    float o0 = a0 * inv + bias[c];
    float o1 = a1 * inv + bias[c + 1];

    int g = batch[n];
    atomicAdd(&g_pool[g * HID + c],     o0);
    atomicAdd(&g_pool[g * HID + c + 1], o1);
    if (lane == 0) atomicAdd(&g_cnt[g], 1.f);
}

// ---------------- MLP head: one block per graph ----------------
__global__ void head_kernel(const float* __restrict__ gf,
                            const float* __restrict__ w1, const float* __restrict__ b1,
                            const float* __restrict__ w2, const float* __restrict__ b2,
                            float* __restrict__ out)
{
    int g = blockIdx.x;
    int j = threadIdx.x;
    __shared__ float pl[HID];
    __shared__ float z[HID];

    float cm = fmaxf(g_cnt[g], 1.f);
    pl[j] = g_pool[g * HID + j] / cm;
    __syncthreads();

    float acc = b1[j];
    #pragma unroll 8
    for (int k = 0; k < HID; k++)   acc += pl[k] * w1[k * HID + j];
    #pragma unroll
    for (int k = 0; k < GFEAT; k++) acc += gf[g * GFEAT + k] * w1[(HID + k) * HID + j];
    z[j] = fmaxf(acc, 0.f);
    __syncthreads();

    if (j < NCLS) {
        float o = b2[j];
        #pragma unroll 8
        for (int k = 0; k < HID; k++) o += z[k] * w2[k * NCLS + j];
        out[g * NCLS + j] = o;
    }
}

// ---------------- launcher ----------------
extern "C" void kernel_launch(void* const* d_in, const int* in_sizes, int n_in,
                              void* d_out, int out_size)
{
    const float* x     = (const float*)d_in[0];
    const int*   ei    = (const int*)  d_in[1];
    const int*   batch = (const int*)  d_in[2];
    const float* gf    = (const float*)d_in[3];
    const float* W1l   = (const float*)d_in[4];
    const float* b1l   = (const float*)d_in[5];
    const float* W1r   = (const float*)d_in[6];
    const float* b1r   = (const float*)d_in[7];
    const float* att1  = (const float*)d_in[8];
    const float* bias1 = (const float*)d_in[9];
    const float* W2l   = (const float*)d_in[10];
    const float* b2l   = (const float*)d_in[11];
    const float* W2r   = (const float*)d_in[12];
    const float* b2r   = (const float*)d_in[13];
    const float* att2  = (const float*)d_in[14];
    const float* bias2 = (const float*)d_in[15];
    const float* l1W   = (const float*)d_in[16];
    const float* l1b   = (const float*)d_in[17];
    const float* l2W   = (const float*)d_in[18];
    const float* l2b   = (const float*)d_in[19];
    float* out = (float*)d_out;

    const int NSCAN = (NNODES + 1023) / 1024;   // 20
    const int NBG   = (NNODES + 127) / 128;     // 157

    zero_kernel      <<<(NNODES + 255) / 256, 256>>>();
    count_kernel     <<<(ETOT + 255) / 256, 256>>>(ei);
    scan_block_kernel<<<NSCAN, 1024>>>();
    scan_top_kernel  <<<1, 32>>>(NSCAN);
    scan_add_kernel  <<<NSCAN, 1024>>>();
    scatter_kernel   <<<(ETOT + 255) / 256, 256>>>(ei);

    gemm_tc_kernel<<<dim3(NBG, 8), 256>>>(1, x, W1l, b1l, W1r, b1r);
    edge1_kernel<<<NNODES / 4, 256>>>(att1, bias1);

    gemm_tc_kernel<<<dim3(NBG, 1), 256>>>(2, x, W2l, b2l, W2r, b2r);
    edge2_kernel<<<NNODES / 8, 256>>>(att2, bias2, batch);

    head_kernel<<<NGRAPH, HID>>>(gf, l1W, l1b, l2W, l2b, out);
}